// round 8
// baseline (speedup 1.0000x reference)
#include <cuda_runtime.h>

#define BB 64
#define NP 576
#define DD 512
#define MM 16
#define NCHUNK 18            // 32-patch chunks per batch = 3 blocks x 6 warps

__device__ float    g_scores[BB*BB];
__device__ float    g_pooled[BB*NP];
__device__ float    g_sesum[BB*MM];      // per-noun sum(exp) accum (self-resetting)
__device__ float    g_t5 [BB*MM*NCHUNK*5];
__device__ double   g_accs[4];           // [0]=contrast,[1]=mask,[2]=clip,[3]=triplet (self-resetting)
__device__ unsigned g_mcnt;              // completed k_fuse blocks (self-resetting)

// ---------------- helpers ----------------
__device__ __forceinline__ float dot4(float4 a, float4 b){
    return a.x*b.x + a.y*b.y + a.z*b.z + a.w*b.w;
}
__device__ __forceinline__ void top5_insert(float t[5], float a){
    #pragma unroll
    for (int q = 0; q < 5; ++q){
        float mx = fmaxf(t[q], a);
        a        = fminf(t[q], a);
        t[q] = mx;
    }
}
__device__ __forceinline__ float warp_top5_sum(float t[5], int lane, float* write5){
    float total = 0.0f;
    #pragma unroll
    for (int it = 0; it < 5; ++it){
        float v = t[0]; int who = lane;
        #pragma unroll
        for (int d = 16; d >= 1; d >>= 1){
            float ov = __shfl_xor_sync(0xffffffffu, v,   d);
            int   ow = __shfl_xor_sync(0xffffffffu, who, d);
            if (ov > v || (ov == v && ow < who)){ v = ov; who = ow; }
        }
        total += v;
        if (write5 && lane == 0) write5[it] = v;
        if (lane == who){ t[0]=t[1]; t[1]=t[2]; t[2]=t[3]; t[3]=t[4]; t[4]=-1e30f; }
    }
    return total;
}
__device__ __forceinline__ void mma_tf32(float c[4], float a0, float a1, float a2, float a3,
                                         float b0, float b1){
    asm volatile(
        "mma.sync.aligned.m16n8k8.row.col.f32.tf32.tf32.f32 "
        "{%0,%1,%2,%3}, {%4,%5,%6,%7}, {%8,%9}, {%0,%1,%2,%3};"
        : "+f"(c[0]), "+f"(c[1]), "+f"(c[2]), "+f"(c[3])
        : "r"(__float_as_uint(a0)), "r"(__float_as_uint(a1)),
          "r"(__float_as_uint(a2)), "r"(__float_as_uint(a3)),
          "r"(__float_as_uint(b0)), "r"(__float_as_uint(b1)));
}

// =======================================================================
// Kernel 1: per-batch GEMM tiles + stats.  grid (4,64), 192 thr (R4 shape).
//   bx in [0,3): 192 patches x 16 nouns via tf32 MMA (32 patches/warp)
//   bx == 3   : row b of global scores
// =======================================================================
__global__ __launch_bounds__(192, 3)
void k_sim(const float* __restrict__ patch, const float* __restrict__ noun,
           const float* __restrict__ img,   const float* __restrict__ txt){
    const int b    = blockIdx.y;
    const int lane = threadIdx.x & 31;
    const int w    = threadIdx.x >> 5;       // 0..5

    if (blockIdx.x == 3){
        const float4* ip = reinterpret_cast<const float4*>(img + (size_t)b * DD);
        float4 a0 = ip[lane], a1 = ip[lane+32], a2 = ip[lane+64], a3 = ip[lane+96];
        for (int j = w; j < BB; j += 6){
            const float4* tp = reinterpret_cast<const float4*>(txt + (size_t)j * DD);
            float s = dot4(a0, tp[lane]) + dot4(a1, tp[lane+32])
                    + dot4(a2, tp[lane+64]) + dot4(a3, tp[lane+96]);
            #pragma unroll
            for (int d = 16; d >= 1; d >>= 1) s += __shfl_xor_sync(0xffffffffu, s, d);
            if (lane == 0) g_scores[b * BB + j] = s;
        }
        return;
    }

    const int q   = lane & 3;       // col-group / k-selector
    const int gid = lane >> 2;      // row-group / noun-selector
    const int rowbase = blockIdx.x * 192 + w * 32;

    const float4* A0 = reinterpret_cast<const float4*>(patch + ((size_t)b*NP + rowbase + gid) * DD);
    const float4* A1 = A0 + 8  * (DD/4);
    const float4* A2 = A0 + 16 * (DD/4);
    const float4* A3 = A0 + 24 * (DD/4);
    const float4* B0 = reinterpret_cast<const float4*>(noun + ((size_t)b*MM + gid) * DD);
    const float4* B1 = B0 + 8 * (DD/4);

    float c00[4] = {0,0,0,0};
    float c01[4] = {0,0,0,0};
    float c10[4] = {0,0,0,0};
    float c11[4] = {0,0,0,0};

    #pragma unroll 4
    for (int p = 0; p < 32; ++p){
        const int o = 4*p + q;
        float4 a0 = A0[o];
        float4 a1 = A1[o];
        float4 a2 = A2[o];
        float4 a3 = A3[o];
        float4 b0 = B0[o];
        float4 b1 = B1[o];
        mma_tf32(c00, a0.x, a1.x, a0.y, a1.y, b0.x, b0.y);
        mma_tf32(c01, a0.x, a1.x, a0.y, a1.y, b1.x, b1.y);
        mma_tf32(c10, a2.x, a3.x, a2.y, a3.y, b0.x, b0.y);
        mma_tf32(c11, a2.x, a3.x, a2.y, a3.y, b1.x, b1.y);
        mma_tf32(c00, a0.z, a1.z, a0.w, a1.w, b0.z, b0.w);
        mma_tf32(c01, a0.z, a1.z, a0.w, a1.w, b1.z, b1.w);
        mma_tf32(c10, a2.z, a3.z, a2.w, a3.w, b0.z, b0.w);
        mma_tf32(c11, a2.z, a3.z, a2.w, a3.w, b1.z, b1.w);
    }

    const float INVT = (float)(1.0 / 0.07);
    #pragma unroll
    for (int i = 0; i < 4; ++i){
        c00[i] *= INVT; c01[i] *= INVT; c10[i] *= INVT; c11[i] *= INVT;
    }

    const int chunk = blockIdx.x * 6 + w;

    // per-noun column stats over this warp's 32 patches (max-free sum-exp + top5)
    #pragma unroll
    for (int u = 0; u < 4; ++u){
        float v0, v1, v2, v3; int col;
        if      (u == 0){ col = 2*q;     v0 = c00[0]; v1 = c00[2]; v2 = c10[0]; v3 = c10[2]; }
        else if (u == 1){ col = 2*q + 1; v0 = c00[1]; v1 = c00[3]; v2 = c10[1]; v3 = c10[3]; }
        else if (u == 2){ col = 2*q + 8; v0 = c01[0]; v1 = c01[2]; v2 = c11[0]; v3 = c11[2]; }
        else            { col = 2*q + 9; v0 = c01[1]; v1 = c01[3]; v2 = c11[1]; v3 = c11[3]; }

        float se = __expf(v0) + __expf(v1) + __expf(v2) + __expf(v3);
        #pragma unroll
        for (int d = 4; d <= 16; d <<= 1) se += __shfl_xor_sync(0xffffffffu, se, d);

        float t[5] = {-1e30f, -1e30f, -1e30f, -1e30f, -1e30f};
        top5_insert(t, v0); top5_insert(t, v1); top5_insert(t, v2); top5_insert(t, v3);
        #pragma unroll
        for (int d = 4; d <= 16; d <<= 1){
            float o0 = __shfl_xor_sync(0xffffffffu, t[0], d);
            float o1 = __shfl_xor_sync(0xffffffffu, t[1], d);
            float o2 = __shfl_xor_sync(0xffffffffu, t[2], d);
            float o3 = __shfl_xor_sync(0xffffffffu, t[3], d);
            float o4 = __shfl_xor_sync(0xffffffffu, t[4], d);
            top5_insert(t, o0); top5_insert(t, o1); top5_insert(t, o2);
            top5_insert(t, o3); top5_insert(t, o4);
        }
        if (gid == 0){
            atomicAdd(&g_sesum[b * MM + col], se);
            int base = (b * MM + col) * NCHUNK + chunk;
            #pragma unroll
            for (int i = 0; i < 5; ++i) g_t5[base*5 + i] = t[i];
        }
    }

    // pooled row sums over all 16 nouns (scaled space)
    float r0 = c00[0] + c00[1] + c01[0] + c01[1];
    float r1 = c00[2] + c00[3] + c01[2] + c01[3];
    float r2 = c10[0] + c10[1] + c11[0] + c11[1];
    float r3 = c10[2] + c10[3] + c11[2] + c11[3];
    #pragma unroll
    for (int d = 1; d <= 2; d <<= 1){
        r0 += __shfl_xor_sync(0xffffffffu, r0, d);
        r1 += __shfl_xor_sync(0xffffffffu, r1, d);
        r2 += __shfl_xor_sync(0xffffffffu, r2, d);
        r3 += __shfl_xor_sync(0xffffffffu, r3, d);
    }
    if (q == 0){
        float* pp = g_pooled + b * NP + rowbase + gid;
        pp[0]  = r0 * (1.0f/16.0f);
        pp[8]  = r1 * (1.0f/16.0f);
        pp[16] = r2 * (1.0f/16.0f);
        pp[24] = r3 * (1.0f/16.0f);
    }
}

// =======================================================================
// Kernel 2: 64 fully-parallel blocks (256 thr). Block b does:
//   A: per-noun top5 merge + lse (from g_sesum)     -> g_accs[0]
//   B: pooled softplus + top5                        -> g_accs[1]
//   C: row-b/col-b contrastive terms (w0/w1),        -> g_accs[2]
//      row-b triplet terms (w2)                      -> g_accs[3]
//   Last arriver writes out[0..2] and resets state.
// =======================================================================
__global__ __launch_bounds__(256)
void k_fuse(const float* __restrict__ logit_scale, const int* __restrict__ idx,
            float* __restrict__ out){
    const int b    = blockIdx.x;
    const int lane = threadIdx.x & 31;
    const int w    = threadIdx.x >> 5;     // 0..7
    const int tid  = threadIdx.x;

    __shared__ float s_red[8];
    __shared__ float s_sp[8];
    __shared__ float s_top[8 * 5];
    __shared__ int   sidx[64];
    __shared__ float s_part[3];            // [0]=0.5*li2t, [1]=0.5*lt2i, [2]=triplet row

    if (tid < 64) sidx[tid] = idx[tid];

    // ---- part A: per-noun top5 merge over 18 chunks + lse (m = w, w+8) ----
    float contrib = 0.0f;
    #pragma unroll
    for (int mi = 0; mi < 2; ++mi){
        const int m = w + mi * 8;
        const int base = (b * MM + m) * NCHUNK;
        float t[5] = {-1e30f, -1e30f, -1e30f, -1e30f, -1e30f};
        if (lane < NCHUNK){
            #pragma unroll
            for (int i = 0; i < 5; ++i) top5_insert(t, g_t5[(base + lane)*5 + i]);
        }
        float tsum = warp_top5_sum(t, lane, nullptr);
        if (lane == 0){
            float ssum = g_sesum[b * MM + m];
            g_sesum[b * MM + m] = 0.0f;          // reset for next replay
            contrib += 5.0f * __logf(ssum) - tsum;
        }
    }
    if (lane == 0) s_red[w] = contrib;

    // ---- part B: pooled softplus + top5 over 576 ----
    float u[5] = {-1e30f, -1e30f, -1e30f, -1e30f, -1e30f};
    float sp = 0.0f;
    #pragma unroll
    for (int rep = 0; rep < 3; ++rep){
        int n = tid + rep * 256;
        if (n < NP){
            float x = g_pooled[b * NP + n];
            sp += fmaxf(x, 0.0f) + __logf(1.0f + __expf(-fabsf(x)));
            top5_insert(u, x);
        }
    }
    #pragma unroll
    for (int d = 16; d >= 1; d >>= 1) sp += __shfl_xor_sync(0xffffffffu, sp, d);
    if (lane == 0) s_sp[w] = sp;
    warp_top5_sum(u, lane, &s_top[w * 5]);
    __syncthreads();

    const float s = logit_scale[0];
    const int myid = sidx[b];

    if (w == 0){
        // row b of logits: li2t
        float l1 = s * g_scores[b * BB + lane];
        float l2 = s * g_scores[b * BB + lane + 32];
        bool  m1 = (sidx[lane]      == myid);
        bool  m2 = (sidx[lane + 32] == myid);
        float rs = __expf(l1) + __expf(l2);
        float rm = (m1 ? l1 : 0.0f) + (m2 ? l2 : 0.0f);
        float rc = (float)(m1 + m2);
        #pragma unroll
        for (int d = 16; d >= 1; d >>= 1){
            rs += __shfl_xor_sync(0xffffffffu, rs, d);
            rm += __shfl_xor_sync(0xffffffffu, rm, d);
            rc += __shfl_xor_sync(0xffffffffu, rc, d);
        }
        if (lane == 0) s_part[0] = 0.5f * (__logf(rs) - rm / rc);
    } else if (w == 1){
        // column b of logits: lt2i
        float l1 = s * g_scores[lane * BB + b];
        float l2 = s * g_scores[(lane + 32) * BB + b];
        bool  m1 = (sidx[lane]      == myid);
        bool  m2 = (sidx[lane + 32] == myid);
        float rs = __expf(l1) + __expf(l2);
        float rm = (m1 ? l1 : 0.0f) + (m2 ? l2 : 0.0f);
        float rc = (float)(m1 + m2);
        #pragma unroll
        for (int d = 16; d >= 1; d >>= 1){
            rs += __shfl_xor_sync(0xffffffffu, rs, d);
            rm += __shfl_xor_sync(0xffffffffu, rm, d);
            rc += __shfl_xor_sync(0xffffffffu, rc, d);
        }
        if (lane == 0) s_part[1] = 0.5f * (__logf(rs) - rm / rc);
    } else if (w == 2){
        // triplet: row b of cost_s + row b of cost_im
        float db = g_scores[b * BB + b];
        float mt = 0.0f;
        #pragma unroll
        for (int rep = 0; rep < 2; ++rep){
            int j = lane + rep * 32;
            if (j != b){
                float v  = g_scores[b * BB + j];
                float dj = g_scores[j * BB + j];
                mt += fmaxf(0.0f, 0.1f + v - db) + fmaxf(0.0f, 0.1f + v - dj);
            }
        }
        #pragma unroll
        for (int d = 16; d >= 1; d >>= 1) mt += __shfl_xor_sync(0xffffffffu, mt, d);
        if (lane == 0) s_part[2] = mt;
    } else if (w == 3){
        // merge per-warp top5s + softplus + part-A sums
        float qq[5] = {-1e30f, -1e30f, -1e30f, -1e30f, -1e30f};
        // 8 warps * 5 = 40 entries
        // (s_top written pre-sync)
        if (lane < 40) top5_insert(qq, s_top[lane]);
        float ftop = warp_top5_sum(qq, lane, nullptr);

        float spt = (lane < 8) ? s_sp[lane]  : 0.0f;
        float crt = (lane < 8) ? s_red[lane] : 0.0f;
        #pragma unroll
        for (int d = 16; d >= 1; d >>= 1){
            spt += __shfl_xor_sync(0xffffffffu, spt, d);
            crt += __shfl_xor_sync(0xffffffffu, crt, d);
        }
        if (lane == 0){
            atomicAdd(&g_accs[0], (double)crt);
            atomicAdd(&g_accs[1], (double)(spt - ftop));
        }
    }
    __syncthreads();

    if (tid == 0){
        atomicAdd(&g_accs[2], (double)(s_part[0] + s_part[1]));
        atomicAdd(&g_accs[3], (double)s_part[2]);
        __threadfence();
        unsigned old = atomicAdd(&g_mcnt, 1u);
        if (old == 63u){
            __threadfence();
            double clip = atomicAdd(&g_accs[2], 0.0);
            double trip = atomicAdd(&g_accs[3], 0.0);
            double ctr  = atomicAdd(&g_accs[0], 0.0);
            double msk  = atomicAdd(&g_accs[1], 0.0);
            out[0] = (float)(clip / 64.0);
            out[1] = (float)(0.5 * trip);
            out[2] = (float)(0.6 * ctr / (double)(BB * MM) + 0.4 * msk / (double)(BB * NP));
            g_accs[0] = 0.0; g_accs[1] = 0.0; g_accs[2] = 0.0; g_accs[3] = 0.0;
            g_mcnt = 0u;
            __threadfence();
        }
    }
}

// =======================================================================
extern "C" void kernel_launch(void* const* d_in, const int* in_sizes, int n_in,
                              void* d_out, int out_size){
    (void)in_sizes; (void)n_in; (void)out_size;
    const float* patch = (const float*)d_in[0];
    const float* noun  = (const float*)d_in[1];
    const float* img   = (const float*)d_in[2];
    const float* txt   = (const float*)d_in[3];
    const float* lsc   = (const float*)d_in[4];
    const int*   idx   = (const int*)d_in[5];
    float* out = (float*)d_out;

    dim3 gsim(4, 64);
    k_sim<<<gsim, 192>>>(patch, noun, img, txt);
    k_fuse<<<64, 256>>>(lsc, idx, out);
}

// round 9
// speedup vs baseline: 1.9736x; 1.9736x over previous
#include <cuda_runtime.h>

#define BB 64
#define NP 576
#define DD 512
#define MM 16
#define NCHUNK 18            // 32-patch chunks per batch = 3 blocks x 6 warps

__device__ float  g_scores[BB*BB];
__device__ float  g_pooled[BB*NP];
__device__ float  g_mx [BB*MM*NCHUNK];
__device__ float  g_se [BB*MM*NCHUNK];
__device__ float  g_t5 [BB*MM*NCHUNK*5];
__device__ double g_accs[4];   // [0]=fine contrast,[1]=mask,[2]=clip,[3]=triplet; zero-init, reset by k_out

// ---------------- helpers ----------------
__device__ __forceinline__ float dot4(float4 a, float4 b){
    return a.x*b.x + a.y*b.y + a.z*b.z + a.w*b.w;
}
__device__ __forceinline__ void top5_insert(float t[5], float a){
    #pragma unroll
    for (int q = 0; q < 5; ++q){
        float mx = fmaxf(t[q], a);
        a        = fminf(t[q], a);
        t[q] = mx;
    }
}
__device__ __forceinline__ float warp_top5_sum(float t[5], int lane, float* write5){
    float total = 0.0f;
    #pragma unroll
    for (int it = 0; it < 5; ++it){
        float v = t[0]; int who = lane;
        #pragma unroll
        for (int d = 16; d >= 1; d >>= 1){
            float ov = __shfl_xor_sync(0xffffffffu, v,   d);
            int   ow = __shfl_xor_sync(0xffffffffu, who, d);
            if (ov > v || (ov == v && ow < who)){ v = ov; who = ow; }
        }
        total += v;
        if (write5 && lane == 0) write5[it] = v;
        if (lane == who){ t[0]=t[1]; t[1]=t[2]; t[2]=t[3]; t[3]=t[4]; t[4]=-1e30f; }
    }
    return total;
}
__device__ __forceinline__ void mma_tf32(float c[4], float a0, float a1, float a2, float a3,
                                         float b0, float b1){
    asm volatile(
        "mma.sync.aligned.m16n8k8.row.col.f32.tf32.tf32.f32 "
        "{%0,%1,%2,%3}, {%4,%5,%6,%7}, {%8,%9}, {%0,%1,%2,%3};"
        : "+f"(c[0]), "+f"(c[1]), "+f"(c[2]), "+f"(c[3])
        : "r"(__float_as_uint(a0)), "r"(__float_as_uint(a1)),
          "r"(__float_as_uint(a2)), "r"(__float_as_uint(a3)),
          "r"(__float_as_uint(b0)), "r"(__float_as_uint(b1)));
}

// =======================================================================
// Kernel 1: EXACT R4 k_sim. grid (4,64), 192 thr.
// =======================================================================
__global__ __launch_bounds__(192, 3)
void k_sim(const float* __restrict__ patch, const float* __restrict__ noun,
           const float* __restrict__ img,   const float* __restrict__ txt){
    const int b    = blockIdx.y;
    const int lane = threadIdx.x & 31;
    const int w    = threadIdx.x >> 5;       // 0..5

    if (blockIdx.x == 3){
        const float4* ip = reinterpret_cast<const float4*>(img + (size_t)b * DD);
        float4 a0 = ip[lane], a1 = ip[lane+32], a2 = ip[lane+64], a3 = ip[lane+96];
        for (int j = w; j < BB; j += 6){
            const float4* tp = reinterpret_cast<const float4*>(txt + (size_t)j * DD);
            float s = dot4(a0, tp[lane]) + dot4(a1, tp[lane+32])
                    + dot4(a2, tp[lane+64]) + dot4(a3, tp[lane+96]);
            #pragma unroll
            for (int d = 16; d >= 1; d >>= 1) s += __shfl_xor_sync(0xffffffffu, s, d);
            if (lane == 0) g_scores[b * BB + j] = s;
        }
        return;
    }

    const int q   = lane & 3;
    const int gid = lane >> 2;
    const int rowbase = blockIdx.x * 192 + w * 32;

    const float4* A0 = reinterpret_cast<const float4*>(patch + ((size_t)b*NP + rowbase + gid) * DD);
    const float4* A1 = A0 + 8  * (DD/4);
    const float4* A2 = A0 + 16 * (DD/4);
    const float4* A3 = A0 + 24 * (DD/4);
    const float4* B0 = reinterpret_cast<const float4*>(noun + ((size_t)b*MM + gid) * DD);
    const float4* B1 = B0 + 8 * (DD/4);

    float c00[4] = {0,0,0,0};
    float c01[4] = {0,0,0,0};
    float c10[4] = {0,0,0,0};
    float c11[4] = {0,0,0,0};

    #pragma unroll 4
    for (int p = 0; p < 32; ++p){
        const int o = 4*p + q;
        float4 a0 = A0[o];
        float4 a1 = A1[o];
        float4 a2 = A2[o];
        float4 a3 = A3[o];
        float4 b0 = B0[o];
        float4 b1 = B1[o];
        mma_tf32(c00, a0.x, a1.x, a0.y, a1.y, b0.x, b0.y);
        mma_tf32(c01, a0.x, a1.x, a0.y, a1.y, b1.x, b1.y);
        mma_tf32(c10, a2.x, a3.x, a2.y, a3.y, b0.x, b0.y);
        mma_tf32(c11, a2.x, a3.x, a2.y, a3.y, b1.x, b1.y);
        mma_tf32(c00, a0.z, a1.z, a0.w, a1.w, b0.z, b0.w);
        mma_tf32(c01, a0.z, a1.z, a0.w, a1.w, b1.z, b1.w);
        mma_tf32(c10, a2.z, a3.z, a2.w, a3.w, b0.z, b0.w);
        mma_tf32(c11, a2.z, a3.z, a2.w, a3.w, b1.z, b1.w);
    }

    const float INVT = (float)(1.0 / 0.07);
    #pragma unroll
    for (int i = 0; i < 4; ++i){
        c00[i] *= INVT; c01[i] *= INVT; c10[i] *= INVT; c11[i] *= INVT;
    }

    const int chunk = blockIdx.x * 6 + w;

    #pragma unroll
    for (int u = 0; u < 4; ++u){
        float v0, v1, v2, v3; int col;
        if      (u == 0){ col = 2*q;     v0 = c00[0]; v1 = c00[2]; v2 = c10[0]; v3 = c10[2]; }
        else if (u == 1){ col = 2*q + 1; v0 = c00[1]; v1 = c00[3]; v2 = c10[1]; v3 = c10[3]; }
        else if (u == 2){ col = 2*q + 8; v0 = c01[0]; v1 = c01[2]; v2 = c11[0]; v3 = c11[2]; }
        else            { col = 2*q + 9; v0 = c01[1]; v1 = c01[3]; v2 = c11[1]; v3 = c11[3]; }

        float mx = fmaxf(fmaxf(v0, v1), fmaxf(v2, v3));
        #pragma unroll
        for (int d = 4; d <= 16; d <<= 1) mx = fmaxf(mx, __shfl_xor_sync(0xffffffffu, mx, d));
        float se = __expf(v0 - mx) + __expf(v1 - mx) + __expf(v2 - mx) + __expf(v3 - mx);
        #pragma unroll
        for (int d = 4; d <= 16; d <<= 1) se += __shfl_xor_sync(0xffffffffu, se, d);

        float t[5] = {-1e30f, -1e30f, -1e30f, -1e30f, -1e30f};
        top5_insert(t, v0); top5_insert(t, v1); top5_insert(t, v2); top5_insert(t, v3);
        #pragma unroll
        for (int d = 4; d <= 16; d <<= 1){
            float o0 = __shfl_xor_sync(0xffffffffu, t[0], d);
            float o1 = __shfl_xor_sync(0xffffffffu, t[1], d);
            float o2 = __shfl_xor_sync(0xffffffffu, t[2], d);
            float o3 = __shfl_xor_sync(0xffffffffu, t[3], d);
            float o4 = __shfl_xor_sync(0xffffffffu, t[4], d);
            top5_insert(t, o0); top5_insert(t, o1); top5_insert(t, o2);
            top5_insert(t, o3); top5_insert(t, o4);
        }
        if (gid == 0){
            int base = (b * MM + col) * NCHUNK + chunk;
            g_mx[base] = mx;
            g_se[base] = se;
            #pragma unroll
            for (int i = 0; i < 5; ++i) g_t5[base*5 + i] = t[i];
        }
    }

    float r0 = c00[0] + c00[1] + c01[0] + c01[1];
    float r1 = c00[2] + c00[3] + c01[2] + c01[3];
    float r2 = c10[0] + c10[1] + c11[0] + c11[1];
    float r3 = c10[2] + c10[3] + c11[2] + c11[3];
    #pragma unroll
    for (int d = 1; d <= 2; d <<= 1){
        r0 += __shfl_xor_sync(0xffffffffu, r0, d);
        r1 += __shfl_xor_sync(0xffffffffu, r1, d);
        r2 += __shfl_xor_sync(0xffffffffu, r2, d);
        r3 += __shfl_xor_sync(0xffffffffu, r3, d);
    }
    if (q == 0){
        float* pp = g_pooled + b * NP + rowbase + gid;
        pp[0]  = r0 * (1.0f/16.0f);
        pp[8]  = r1 * (1.0f/16.0f);
        pp[16] = r2 * (1.0f/16.0f);
        pp[24] = r3 * (1.0f/16.0f);
    }
}

// =======================================================================
// Kernel 2: grid 68, 768 threads (24 warps). No counters, no fences.
//  blocks 0..63 : batch merge. warps 0-15 = noun m part A; warps 16-23 = part B.
//  blocks 64..67: contrastive + triplet, warp-per-row (16 rows/block).
// =======================================================================
__global__ __launch_bounds__(768)
void k_tail(const float* __restrict__ logit_scale, const int* __restrict__ idx){
    const int lane = threadIdx.x & 31;
    const int w    = threadIdx.x >> 5;     // 0..23
    const int tid  = threadIdx.x;

    if (blockIdx.x < 64){
        const int b = blockIdx.x;
        __shared__ float s_red[16];
        __shared__ float s_sp[8];
        __shared__ float s_top[8 * 5];

        if (w < 16){
            // ---- part A: noun m = w ----
            const int base = (b * MM + w) * NCHUNK;
            float mxA = (lane < NCHUNK) ? g_mx[base + lane] : -1e30f;
            float mx = mxA;
            #pragma unroll
            for (int d = 16; d >= 1; d >>= 1) mx = fmaxf(mx, __shfl_xor_sync(0xffffffffu, mx, d));
            float se = (lane < NCHUNK) ? g_se[base + lane] * __expf(mxA - mx) : 0.0f;
            #pragma unroll
            for (int d = 16; d >= 1; d >>= 1) se += __shfl_xor_sync(0xffffffffu, se, d);

            float t[5] = {-1e30f, -1e30f, -1e30f, -1e30f, -1e30f};
            if (lane < NCHUNK){
                #pragma unroll
                for (int i = 0; i < 5; ++i) top5_insert(t, g_t5[(base + lane)*5 + i]);
            }
            float tsum = warp_top5_sum(t, lane, nullptr);
            if (lane == 0) s_red[w] = 5.0f * (mx + __logf(se)) - tsum;
        } else {
            // ---- part B: warp wb = w-16 handles 72 pooled values ----
            const int wb = w - 16;
            const float* pb = g_pooled + b * NP + wb * 72;
            float u[5] = {-1e30f, -1e30f, -1e30f, -1e30f, -1e30f};
            float sp = 0.0f;
            float x0 = pb[lane];
            float x1 = pb[lane + 32];
            sp += fmaxf(x0, 0.0f) + __logf(1.0f + __expf(-fabsf(x0)));
            sp += fmaxf(x1, 0.0f) + __logf(1.0f + __expf(-fabsf(x1)));
            top5_insert(u, x0); top5_insert(u, x1);
            if (lane < 8){
                float x2 = pb[lane + 64];
                sp += fmaxf(x2, 0.0f) + __logf(1.0f + __expf(-fabsf(x2)));
                top5_insert(u, x2);
            }
            #pragma unroll
            for (int d = 16; d >= 1; d >>= 1) sp += __shfl_xor_sync(0xffffffffu, sp, d);
            if (lane == 0) s_sp[wb] = sp;
            warp_top5_sum(u, lane, &s_top[wb * 5]);
        }
        __syncthreads();

        if (w == 0){
            float qq[5] = {-1e30f, -1e30f, -1e30f, -1e30f, -1e30f};
            top5_insert(qq, s_top[lane]);
            if (lane < 8) top5_insert(qq, s_top[lane + 32]);
            float ftop = warp_top5_sum(qq, lane, nullptr);

            float crt = (lane < 16) ? s_red[lane] : 0.0f;
            float spt = (lane < 8)  ? s_sp[lane]  : 0.0f;
            #pragma unroll
            for (int d = 16; d >= 1; d >>= 1){
                crt += __shfl_xor_sync(0xffffffffu, crt, d);
                spt += __shfl_xor_sync(0xffffffffu, spt, d);
            }
            if (lane == 0){
                atomicAdd(&g_accs[0], (double)crt);
                atomicAdd(&g_accs[1], (double)(spt - ftop));
            }
        }
        return;
    }

    // ---------------- contrastive + triplet block ----------------
    __shared__ int   sidx[64];
    __shared__ float s_c[16];
    __shared__ float s_t[16];
    if (tid < 64) sidx[tid] = idx[tid];
    __syncthreads();

    if (w < 16){
        const int r = (blockIdx.x - 64) * 16 + w;
        const float s = logit_scale[0];
        const int myid = sidx[r];
        const bool m1 = (sidx[lane]      == myid);
        const bool m2 = (sidx[lane + 32] == myid);

        // row r of logits
        float v1 = g_scores[r * BB + lane];
        float v2 = g_scores[r * BB + lane + 32];
        float l1 = s * v1, l2 = s * v2;
        float rs = __expf(l1) + __expf(l2);
        float rm = (m1 ? l1 : 0.0f) + (m2 ? l2 : 0.0f);
        float rc = (float)(m1 + m2);
        // column r of logits
        float c1 = s * g_scores[lane * BB + r];
        float c2 = s * g_scores[(lane + 32) * BB + r];
        float cs = __expf(c1) + __expf(c2);
        float cm = (m1 ? c1 : 0.0f) + (m2 ? c2 : 0.0f);
        // triplet row r
        float dr = g_scores[r * BB + r];
        float d1 = g_scores[lane * BB + lane];
        float d2 = g_scores[(lane + 32) * BB + lane + 32];
        float mt = 0.0f;
        if (lane != r)        mt += fmaxf(0.0f, 0.1f + v1 - dr) + fmaxf(0.0f, 0.1f + v1 - d1);
        if (lane + 32 != r)   mt += fmaxf(0.0f, 0.1f + v2 - dr) + fmaxf(0.0f, 0.1f + v2 - d2);

        #pragma unroll
        for (int d = 16; d >= 1; d >>= 1){
            rs += __shfl_xor_sync(0xffffffffu, rs, d);
            rm += __shfl_xor_sync(0xffffffffu, rm, d);
            rc += __shfl_xor_sync(0xffffffffu, rc, d);
            cs += __shfl_xor_sync(0xffffffffu, cs, d);
            cm += __shfl_xor_sync(0xffffffffu, cm, d);
            mt += __shfl_xor_sync(0xffffffffu, mt, d);
        }
        if (lane == 0){
            float li2t = __logf(rs) - rm / rc;
            float lt2i = __logf(cs) - cm / rc;
            s_c[w] = 0.5f * (li2t + lt2i);
            s_t[w] = mt;
        }
    }
    __syncthreads();

    if (w == 0){
        float cc = (lane < 16) ? s_c[lane] : 0.0f;
        float tt = (lane < 16) ? s_t[lane] : 0.0f;
        #pragma unroll
        for (int d = 16; d >= 1; d >>= 1){
            cc += __shfl_xor_sync(0xffffffffu, cc, d);
            tt += __shfl_xor_sync(0xffffffffu, tt, d);
        }
        if (lane == 0){
            atomicAdd(&g_accs[2], (double)cc);
            atomicAdd(&g_accs[3], (double)tt);
        }
    }
}

// =======================================================================
// Kernel 3: tiny combiner. Reads accs, writes out, resets accs.
// =======================================================================
__global__ void k_out(float* __restrict__ out){
    if (threadIdx.x == 0){
        double clip = g_accs[2];
        double trip = g_accs[3];
        double ctr  = g_accs[0];
        double msk  = g_accs[1];
        out[0] = (float)(clip / 64.0);
        out[1] = (float)(0.5 * trip);
        out[2] = (float)(0.6 * ctr / (double)(BB * MM) + 0.4 * msk / (double)(BB * NP));
        g_accs[0] = 0.0; g_accs[1] = 0.0; g_accs[2] = 0.0; g_accs[3] = 0.0;
    }
}

// =======================================================================
extern "C" void kernel_launch(void* const* d_in, const int* in_sizes, int n_in,
                              void* d_out, int out_size){
    (void)in_sizes; (void)n_in; (void)out_size;
    const float* patch = (const float*)d_in[0];
    const float* noun  = (const float*)d_in[1];
    const float* img   = (const float*)d_in[2];
    const float* txt   = (const float*)d_in[3];
    const float* lsc   = (const float*)d_in[4];
    const int*   idx   = (const int*)d_in[5];
    float* out = (float*)d_out;

    dim3 gsim(4, 64);
    k_sim<<<gsim, 192>>>(patch, noun, img, txt);
    k_tail<<<68, 768>>>(lsc, idx);
    k_out<<<1, 32>>>(out);
}